// round 6
// baseline (speedup 1.0000x reference)
#include <cuda_runtime.h>
#include <math.h>

#define BB 64
#define FF 512
#define EE 256
#define HH 8
#define DD 32
#define LL 4

// Precomputed collapsed vectors + per-group handshake flags (zero-initialized)
__device__ float g_kw[EE];   // emb_w @ k_w
__device__ float g_vw[EE];   // emb_w @ v_w
__device__ float g_vb[EE];   // emb_b @ v_w + v_b
__device__ float g_qv[EE];   // emb_b @ q_w + q_b
__device__ __align__(128) unsigned int g_flags[8][32];  // [grp][0], 128B padded
__device__ unsigned int g_done = 0;                     // consumer blocks retired

__device__ __forceinline__ float ex2f(float x) {
    float y;
    asm("ex2.approx.ftz.f32 %0, %1;" : "=f"(y) : "f"(x));
    return y;
}
__device__ __forceinline__ void release_grp(unsigned int* p) {
    asm volatile("red.release.gpu.global.add.u32 [%0], %1;"
                 :: "l"(p), "r"(1u) : "memory");
}
__device__ __forceinline__ unsigned int acquire_ld(const unsigned int* p) {
    unsigned int v;
    asm volatile("ld.acquire.gpu.global.u32 %0, [%1];"
                 : "=r"(v) : "l"(p) : "memory");
    return v;
}

// ---------------------------------------------------------------------------
// Single fused kernel, grid = 72 (one wave), block = 256.
//   blocks 64..71 : producers — block (64+g) computes columns g*32..g*32+31 of
//                   ALL FOUR collapsed vectors, then releases flag g.
//                   Warp w: matrix m = w&3, row-half = w>>2 (128 rows each).
//   blocks  0..63 : consumers — one batch each; warp w = head w needs exactly
//                   column-group w, so it polls flag w autonomously (no block
//                   gate) after finishing its gate-independent prologue.
// ---------------------------------------------------------------------------
__global__ void __launch_bounds__(256, 1)
fused_kernel(const float* __restrict__ features,
             const float* __restrict__ emb_w,
             const float* __restrict__ emb_b,
             const float* __restrict__ q_w,
             const float* __restrict__ q_b,
             const float* __restrict__ k_w,
             const float* __restrict__ v_w,
             const float* __restrict__ v_b,
             const float* __restrict__ attn_w,
             const float* __restrict__ attn_b,
             float* __restrict__ out) {
    const int b    = blockIdx.x;
    const int t    = threadIdx.x;       // 0..255
    const int warp = t >> 5;
    const int lane = t & 31;

    if (b >= BB) {
        // ------------------- producer block (8 total) -------------------
        __shared__ float s_pre[4][2][32];   // [matrix][row-half][col lane]
        const int grp  = b - BB;            // column group 0..7
        const int m    = warp & 3;          // 0:kw 1:vw 2:vb 3:qv
        const int half = warp >> 2;         // row half 0/1
        const int col  = grp * 32 + lane;

        const float* vecsrc = (m <= 1) ? emb_w : emb_b;
        const float* mat    = (m == 0) ? k_w : (m == 3 ? q_w : v_w);
        const float* mp     = mat + (half * 128) * EE + col;

        // this warp's 128 embedding entries: 4 per lane
        float ev0 = vecsrc[half * 128 +  0 + lane];
        float ev1 = vecsrc[half * 128 + 32 + lane];
        float ev2 = vecsrc[half * 128 + 64 + lane];
        float ev3 = vecsrc[half * 128 + 96 + lane];
        // bias prefetch (only used by warps 2,3 / half 0)
        float bias = 0.f;
        if (half == 0) {
            if (m == 2) bias = v_b[col];
            if (m == 3) bias = q_b[col];
        }

        float a0 = 0.f, a1 = 0.f, a2 = 0.f, a3 = 0.f;
        #pragma unroll
        for (int e = 0; e < 32; e++) {
            a0 = fmaf(__shfl_sync(0xffffffffu, ev0, e), mp[(e      ) * EE], a0);
            a1 = fmaf(__shfl_sync(0xffffffffu, ev1, e), mp[(e +  32) * EE], a1);
            a2 = fmaf(__shfl_sync(0xffffffffu, ev2, e), mp[(e +  64) * EE], a2);
            a3 = fmaf(__shfl_sync(0xffffffffu, ev3, e), mp[(e +  96) * EE], a3);
        }
        s_pre[m][half][lane] = (a0 + a1) + (a2 + a3);
        __syncthreads();

        if (half == 0) {                    // warps 0..3 finalize matrix m
            float a = s_pre[m][0][lane] + s_pre[m][1][lane] + bias;
            float* dst = (m == 0) ? g_kw : (m == 1) ? g_vw
                       : (m == 2) ? g_vb : g_qv;
            dst[col] = a;
        }
        __syncthreads();                    // all stores before release
        if (t == 0) release_grp(&g_flags[grp][0]);
        return;
    }

    // ------------------- consumer block (64 total) -------------------
    __shared__ float s_ox[HH], s_hc[HH];

    // Full feature vector per warp: xr[i] = x[lane + 32i] (coalesced)
    const float* xb = features + b * FF;
    float xr[FF / 32];
    #pragma unroll
    for (int i = 0; i < FF / 32; i++) xr[i] = xb[lane + i * 32];

    const int hi = warp * DD + lane;
    float aw = attn_w[hi];
    float ab = attn_b[0];

    // Warp-local stats (gate-independent; overlaps producer latency)
    float S = 0.f, xmax = -1e30f, xmin = 1e30f;
    #pragma unroll
    for (int i = 0; i < FF / 32; i++) {
        S += xr[i];
        xmax = fmaxf(xmax, xr[i]);
        xmin = fminf(xmin, xr[i]);
    }
    #pragma unroll
    for (int o = 16; o > 0; o >>= 1) {
        S   += __shfl_xor_sync(0xffffffffu, S,   o);
        xmax = fmaxf(xmax, __shfl_xor_sync(0xffffffffu, xmax, o));
        xmin = fminf(xmin, __shfl_xor_sync(0xffffffffu, xmin, o));
    }

    // ---- Warp-autonomous gate: wait for THIS head's producer only ----
    while (acquire_ld(&g_flags[warp][0]) == 0u) { }

    // ---- Per-head scalars ----
    float kw = __ldcg(&g_kw[hi]);
    float vw = __ldcg(&g_vw[hi]);
    float vb = __ldcg(&g_vb[hi]);
    float qv = __ldcg(&g_qv[hi]);

    const float scale = 0.17677669529663687f;      // 1/sqrt(32)
    float A0 = qv * kw, P = vw * kw, R = vb * kw, VA = vw * aw, VB = vb * aw;
    #pragma unroll
    for (int o = 16; o > 0; o >>= 1) {
        A0 += __shfl_xor_sync(0xffffffffu, A0, o);
        P  += __shfl_xor_sync(0xffffffffu, P,  o);
        R  += __shfl_xor_sync(0xffffffffu, R,  o);
        VA += __shfl_xor_sync(0xffffffffu, VA, o);
        VB += __shfl_xor_sync(0xffffffffu, VB, o);
    }
    A0 *= scale; P *= scale; R *= scale;

    // ---- L-step scalar softmax recursion (warp-local, tree sums) ----
    const float L2E = 1.4426950408889634f;
    float alpha = A0;
    float m = 0.f;
    #pragma unroll
    for (int it = 0; it < LL; it++) {
        float a2 = alpha * L2E;
        float M2 = (alpha >= 0.f) ? a2 * xmax : a2 * xmin;   // exact max logit
        float w[FF / 32];
        #pragma unroll
        for (int i = 0; i < FF / 32; i++) w[i] = ex2f(fmaf(a2, xr[i], -M2));
        // pairwise trees for sum(w) and sum(x*w)
        float sw0 = w[0] + w[1],   sw1 = w[2] + w[3];
        float sw2 = w[4] + w[5],   sw3 = w[6] + w[7];
        float sw4 = w[8] + w[9],   sw5 = w[10] + w[11];
        float sw6 = w[12] + w[13], sw7 = w[14] + w[15];
        float sw = ((sw0 + sw1) + (sw2 + sw3)) + ((sw4 + sw5) + (sw6 + sw7));
        float t0 = fmaf(xr[1],  w[1],  xr[0]  * w[0]);
        float t1 = fmaf(xr[3],  w[3],  xr[2]  * w[2]);
        float t2 = fmaf(xr[5],  w[5],  xr[4]  * w[4]);
        float t3 = fmaf(xr[7],  w[7],  xr[6]  * w[6]);
        float t4 = fmaf(xr[9],  w[9],  xr[8]  * w[8]);
        float t5 = fmaf(xr[11], w[11], xr[10] * w[10]);
        float t6 = fmaf(xr[13], w[13], xr[12] * w[12]);
        float t7 = fmaf(xr[15], w[15], xr[14] * w[14]);
        float sxw = ((t0 + t1) + (t2 + t3)) + ((t4 + t5) + (t6 + t7));
        #pragma unroll
        for (int o = 16; o > 0; o >>= 1) {
            sw  += __shfl_xor_sync(0xffffffffu, sw,  o);
            sxw += __shfl_xor_sync(0xffffffffu, sxw, o);
        }
        m = __fdividef(sxw, sw);
        alpha = fmaf(m, P, R);
    }

    if (lane == 0) {
        s_ox[warp] = fmaf(m, VA, VB);                          // Qc contribution
        s_hc[warp] = fmaf(S - m, VA, (float)(FF - 1) * VB);    // (v_sum - Qc)
    }
    __syncthreads();

    float ox = ab, cc = ab;
    #pragma unroll
    for (int hh = 0; hh < HH; hh++) { ox += s_ox[hh]; cc += s_hc[hh]; }

    out[b * FF + t]                 = ox;
    out[b * FF + t + 256]           = ox;
    out[BB * FF + b * FF + t]       = cc;
    out[BB * FF + b * FF + t + 256] = cc;

    // ---- Last consumer resets flags for the next graph replay.
    // Safe: every warp of every consumer passed its gate before the final
    // __syncthreads above, so g_done==64 implies no one re-reads g_flags.
    if (t == 0) {
        unsigned int prev = atomicAdd(&g_done, 1u);
        if (prev == BB - 1) {
            #pragma unroll
            for (int g = 0; g < 8; g++) g_flags[g][0] = 0u;
            g_done = 0u;
            __threadfence();
        }
    }
}

extern "C" void kernel_launch(void* const* d_in, const int* in_sizes, int n_in,
                              void* d_out, int out_size) {
    const float* features = (const float*)d_in[0];
    const float* emb_w    = (const float*)d_in[1];
    const float* emb_b    = (const float*)d_in[2];
    const float* q_w      = (const float*)d_in[3];
    const float* q_b      = (const float*)d_in[4];
    const float* k_w      = (const float*)d_in[5];
    // d_in[6] = k_b: cancels in softmax, unused
    const float* v_w      = (const float*)d_in[7];
    const float* v_b      = (const float*)d_in[8];
    const float* attn_w   = (const float*)d_in[9];
    const float* attn_b   = (const float*)d_in[10];
    float* out = (float*)d_out;

    fused_kernel<<<72, 256>>>(features, emb_w, emb_b, q_w, q_b, k_w,
                              v_w, v_b, attn_w, attn_b, out);
}